// round 17
// baseline (speedup 1.0000x reference)
#include <cuda_runtime.h>
#include <cuda_fp16.h>
#include <cstdint>

#define CC    512
#define TT    16
#define PP    576
#define NN    9216
#define CN    4718592
#define NHEAD 8
#define TOTAL 9437184

// ---- GEMM (fp16), BK=64, 2-stage ----
#define GSTR    72                  // halves per SMEM row (144B)
#define GSTAGE_B 36864              // bytes per stage: A 18432 + B 18432
#define GEMM_SMEM (2*GSTAGE_B)      // 73728 B -> 2 blocks/SM

// ---- attention smem (bytes), 3-stage KV ----
#define KROW  72                        // halves per K row (144B)
#define AOFF_K   9216                   // after QS (64*72*2)
#define AOFF_V   (AOFF_K + 3*32*144)    // 23040
#define ATT_SMEM (AOFF_V + 3*64*80)     // 38400 B -> 4 blocks/SM

#define QSCALE 0.18033688f              // 0.125 * log2(e)

__device__ __half g_xt[TOTAL];     // [tok][c] fp16 (x+pos)
__device__ __half g_q[TOTAL];      // [b][t][p][512]  (Q pre-scaled by 0.125*log2e)
__device__ __half g_k[TOTAL];
__device__ __half g_vT[TOTAL];     // [b][t][head][d=64][key=576]
__device__ __half g_attn[TOTAL];   // [tok][c]
__device__ __half g_wr[4*CC*CC];   // fp16 wq*QSCALE, wk, wv, wo

__device__ __forceinline__ uint32_t smem_u32(const void* p){
    uint32_t a;
    asm("{ .reg .u64 t; cvta.to.shared.u64 t, %1; cvt.u32.u64 %0, t; }"
        : "=r"(a) : "l"(p));
    return a;
}
__device__ __forceinline__ uint32_t ldh2(const __half* p){
    return *(const uint32_t*)p;
}
__device__ __forceinline__ float ex2f(float x){
    float r; asm("ex2.approx.f32 %0, %1;" : "=f"(r) : "f"(x)); return r;
}
__device__ __forceinline__ void mmaf16(float4& d,
    uint32_t a0, uint32_t a1, uint32_t a2, uint32_t a3,
    uint32_t b0, uint32_t b1)
{
    asm volatile(
        "mma.sync.aligned.m16n8k16.row.col.f32.f16.f16.f32 "
        "{%0,%1,%2,%3}, {%4,%5,%6,%7}, {%8,%9}, {%0,%1,%2,%3};"
        : "+f"(d.x), "+f"(d.y), "+f"(d.z), "+f"(d.w)
        : "r"(a0), "r"(a1), "r"(a2), "r"(a3), "r"(b0), "r"(b1));
}
__device__ __forceinline__ void ldsm_x4(uint32_t* r, uint32_t addr){
    asm volatile("ldmatrix.sync.aligned.m8n8.x4.shared.b16 {%0,%1,%2,%3}, [%4];"
                 : "=r"(r[0]), "=r"(r[1]), "=r"(r[2]), "=r"(r[3]) : "r"(addr));
}
__device__ __forceinline__ void ldsm_x2(uint32_t* r, uint32_t addr){
    asm volatile("ldmatrix.sync.aligned.m8n8.x2.shared.b16 {%0,%1}, [%2];"
                 : "=r"(r[0]), "=r"(r[1]) : "r"(addr));
}

// ---------------------------------------------------------------------------
// prep: weights -> fp16; wq pre-scaled by 0.125*log2(e)  (exp -> ex2)
// ---------------------------------------------------------------------------
__global__ void prep_w(const float* __restrict__ wq, const float* __restrict__ wk,
                       const float* __restrict__ wv, const float* __restrict__ wo){
    const int i = blockIdx.x * 256 + threadIdx.x;
    g_wr[i]          = __float2half_rn(wq[i] * QSCALE);
    g_wr[262144 + i] = __float2half_rn(wk[i]);
    g_wr[524288 + i] = __float2half_rn(wv[i]);
    g_wr[786432 + i] = __float2half_rn(wo[i]);
}

// ---------------------------------------------------------------------------
// transpose x[b][c][n] + pos[c][t] -> g_xt[b*9216+n][c]  (fp16)
// ---------------------------------------------------------------------------
__global__ __launch_bounds__(256) void transpose_pos(
    const float* __restrict__ x, const float* __restrict__ pos){
    __shared__ float tile[32][33];
    const int n0 = blockIdx.x * 32, c0 = blockIdx.y * 32, b = blockIdx.z;
    const int tx = threadIdx.x & 31, ty = threadIdx.x >> 5;
    const int t = n0 / PP;
#pragma unroll
    for (int i = 0; i < 4; ++i){
        const int c = c0 + ty + i * 8;
        tile[ty + i * 8][tx] = x[((size_t)b * CC + c) * NN + n0 + tx] + pos[c * TT + t];
    }
    __syncthreads();
#pragma unroll
    for (int i = 0; i < 4; ++i){
        const int n = n0 + ty + i * 8;
        g_xt[((size_t)b * NN + n) * CC + c0 + tx] = __float2half_rn(tile[tx][ty + i * 8]);
    }
}

// ---------------------------------------------------------------------------
// fp16 GEMM: m16n8k16, BK=64, 2-stage cp.async, ldmatrix fragments.
// 8 barriers per block. MODE 0: QKV (pr==2 stores V^T); MODE 1: out-proj.
// ---------------------------------------------------------------------------
template<int MODE>
__global__ __launch_bounds__(256, 2) void gemm_mma(
    const float* __restrict__ bi0, const float* __restrict__ bi1,
    const float* __restrict__ bi2, float* __restrict__ o_out)
{
    extern __shared__ char smc[];

    const int tid = threadIdx.x;
    const int m0 = blockIdx.x * 128;
    const int n0 = blockIdx.y * 128;
    const int pr = (MODE == 0) ? blockIdx.z : 3;

    const __half* A  = (MODE == 0 ? g_xt : g_attn) + (size_t)m0 * CC;
    const __half* Bw = g_wr + (size_t)pr * 262144 + (size_t)n0 * CC;
    const float* bias = (MODE == 1) ? bi0 : (pr == 0 ? bi0 : pr == 1 ? bi1 : bi2);

    const int wid = tid >> 5, lane = tid & 31;
    const int wm = wid >> 2, wn = wid & 3;
    const int r = lane >> 2, c = lane & 3;
    const int tr = lane & 15, th = lane >> 4;
    const int bn8 = lane & 7, bh = (lane >> 3) & 1;

    const uint32_t smb = smem_u32(smc);
    const int lrow = tid >> 1;             // 0..127
    const int jb   = (tid & 1) * 4;        // chunks 0-3 or 4-7 (16B each)

    auto load_stage = [&](int kt, int stage){
        const uint32_t ad = smb + (uint32_t)stage * GSTAGE_B + (uint32_t)lrow * 144u + (uint32_t)jb * 16u;
        const uint32_t bd = ad + 18432u;
        const __half* ag = A  + (size_t)lrow * CC + kt * 64 + jb * 8;
        const __half* bg = Bw + (size_t)lrow * CC + kt * 64 + jb * 8;
#pragma unroll
        for (int jj = 0; jj < 4; ++jj){
            asm volatile("cp.async.cg.shared.global [%0], [%1], 16;"
                         :: "r"(ad + jj * 16u), "l"(ag + jj * 8));
            asm volatile("cp.async.cg.shared.global [%0], [%1], 16;"
                         :: "r"(bd + jj * 16u), "l"(bg + jj * 8));
        }
        asm volatile("cp.async.commit_group;");
    };

    float4 acc[4][4];
#pragma unroll
    for (int i = 0; i < 4; ++i)
#pragma unroll
        for (int j = 0; j < 4; ++j) acc[i][j] = make_float4(0.f, 0.f, 0.f, 0.f);

    load_stage(0, 0);

    for (int kt = 0; kt < 8; ++kt){
        asm volatile("cp.async.wait_group 0;" ::: "memory");
        __syncthreads();                     // tile kt ready; buf kt^1 free
        if (kt < 7) load_stage(kt + 1, (kt + 1) & 1);

        const uint32_t smA = smb + (uint32_t)(kt & 1) * GSTAGE_B;
        const uint32_t smB = smA + 18432u;
#pragma unroll
        for (int kp = 0; kp < 4; ++kp){
            uint32_t af[4][4], bf[4][2];
#pragma unroll
            for (int mi = 0; mi < 4; ++mi)
                ldsm_x4(af[mi], smA + (uint32_t)((wm * 64 + mi * 16 + tr) * 144
                                                 + kp * 32 + th * 16));
#pragma unroll
            for (int ni = 0; ni < 4; ++ni)
                ldsm_x2(bf[ni], smB + (uint32_t)((wn * 32 + ni * 8 + bn8) * 144
                                                 + kp * 32 + bh * 16));
#pragma unroll
            for (int mi = 0; mi < 4; ++mi)
#pragma unroll
                for (int ni = 0; ni < 4; ++ni)
                    mmaf16(acc[mi][ni], af[mi][0], af[mi][1], af[mi][2], af[mi][3],
                           bf[ni][0], bf[ni][1]);
        }
    }

    if (MODE == 0 && pr < 2){
        __half* OUT = (pr == 0) ? g_q : g_k;
        const float bsc = (pr == 0) ? QSCALE : 1.0f;
#pragma unroll
        for (int mi = 0; mi < 4; ++mi){
            const int row = m0 + wm * 64 + mi * 16 + r;
#pragma unroll
            for (int ni = 0; ni < 4; ++ni){
                const int col = n0 + wn * 32 + ni * 8 + 2 * c;
                const float b0 = __ldg(bias + col) * bsc, b1 = __ldg(bias + col + 1) * bsc;
                *(half2*)(OUT + (size_t)row * CC + col) =
                    __floats2half2_rn(acc[mi][ni].x + b0, acc[mi][ni].y + b1);
                *(half2*)(OUT + (size_t)(row + 8) * CC + col) =
                    __floats2half2_rn(acc[mi][ni].z + b0, acc[mi][ni].w + b1);
            }
        }
    } else if (MODE == 0){
        // V: transpose through smem, store g_vT[bt][head][d][key]
        __syncthreads();
        __half* tsh = (__half*)smc;          // [128 col][136]
#pragma unroll
        for (int mi = 0; mi < 4; ++mi){
            const int row = wm * 64 + mi * 16 + r;
#pragma unroll
            for (int ni = 0; ni < 4; ++ni){
                const int col = wn * 32 + ni * 8 + 2 * c;
                const float b0 = __ldg(bias + n0 + col), b1 = __ldg(bias + n0 + col + 1);
                tsh[ col      * 136 + row    ] = __float2half_rn(acc[mi][ni].x + b0);
                tsh[(col + 1) * 136 + row    ] = __float2half_rn(acc[mi][ni].y + b1);
                tsh[ col      * 136 + row + 8] = __float2half_rn(acc[mi][ni].z + b0);
                tsh[(col + 1) * 136 + row + 8] = __float2half_rn(acc[mi][ni].w + b1);
            }
        }
        __syncthreads();
        const int c2 = tid >> 1, seg = tid & 1;
        const int ts = m0 + seg * 64;
        const int bt = ts / PP, p0 = ts - bt * PP;
        const int colg = n0 + c2;
        __half* dst = g_vT + ((size_t)bt * NHEAD + (colg >> 6)) * (64 * PP)
                    + (size_t)(colg & 63) * PP + p0;
        const __half* src = tsh + c2 * 136 + seg * 64;
#pragma unroll
        for (int j8 = 0; j8 < 8; ++j8)
            *(uint4*)(dst + j8 * 8) = *(const uint4*)(src + j8 * 8);
    } else {
        const int b = (m0 >= NN) ? 1 : 0;
        const int tbase = m0 - b * NN;
#pragma unroll
        for (int mi = 0; mi < 4; ++mi){
            const int ltok = wm * 64 + mi * 16 + r;
            float* ob = o_out + (size_t)b * CN + tbase + ltok;
#pragma unroll
            for (int ni = 0; ni < 4; ++ni){
                const int col = n0 + wn * 32 + ni * 8 + 2 * c;
                const float b0 = __ldg(bias + col), b1 = __ldg(bias + col + 1);
                ob[(size_t)col * NN]           = acc[mi][ni].x + b0;
                ob[(size_t)(col + 1) * NN]     = acc[mi][ni].y + b1;
                ob[(size_t)col * NN + 8]       = acc[mi][ni].z + b0;
                ob[(size_t)(col + 1) * NN + 8] = acc[mi][ni].w + b1;
            }
        }
    }
}

// ---------------------------------------------------------------------------
// fp16 flash attention: register-resident P, 3-stage KV pipeline, ex2 softmax.
// ---------------------------------------------------------------------------
__global__ __launch_bounds__(128, 4) void attn_mma()
{
    extern __shared__ char smc[];
    __half* QS = (__half*)smc;                 // [64][72] (prologue only)
    __half* Kt = (__half*)(smc + AOFF_K);      // [3][32][KROW=72]
    __half* Vt = (__half*)(smc + AOFF_V);      // [3][64][40] (V^T rows=d)

    const int tid  = threadIdx.x;
    const int lane = tid & 31, wid = tid >> 5;
    const int g = lane >> 2, c = lane & 3;

    const int bnt = blockIdx.y, qt = blockIdx.x;
    const int b = bnt >> 7, n = (bnt >> 4) & 7, t = bnt & 15;
    const int bt = b * TT + t;
    const size_t base = (size_t)bt * PP * CC;
    const int col0 = n * 64;
    const __half* Qg = g_q + base + (size_t)qt * 64 * CC + col0;
    const __half* Kg = g_k + base + col0;
    const __half* Vg = g_vT + ((size_t)bt * NHEAD + n) * (64 * PP);

    const uint32_t sb = smem_u32(smc);

    auto load_kv = [&](int kb, int buf){
#pragma unroll
        for (int it = 0; it < 4; ++it){
            const int f = tid + it * 128;
            if (f < 256){
                const int row = f >> 3, ch = f & 7;
                const uint32_t kd = sb + AOFF_K + (uint32_t)(buf * 32 + row) * 144u + ch * 16u;
                const __half* ks = Kg + (size_t)(kb * 32 + row) * CC + ch * 8;
                asm volatile("cp.async.cg.shared.global [%0], [%1], 16;" :: "r"(kd), "l"(ks));
            } else {
                const int fv = f - 256;
                const int row = fv >> 2, ch = fv & 3;
                const uint32_t vd = sb + AOFF_V + (uint32_t)(buf * 64 + row) * 80u + ch * 16u;
                const __half* vs = Vg + (size_t)row * PP + kb * 32 + ch * 8;
                asm volatile("cp.async.cg.shared.global [%0], [%1], 16;" :: "r"(vd), "l"(vs));
            }
        }
        asm volatile("cp.async.commit_group;");
    };

    load_kv(0, 0);
    load_kv(1, 1);

#pragma unroll
    for (int it = 0; it < 4; ++it){
        const int f = tid + it * 128;
        const int row = f >> 3, ch = f & 7;
        *(uint4*)(QS + row * 72 + ch * 8) = *(const uint4*)(Qg + (size_t)row * CC + ch * 8);
    }
    __syncthreads();

    const int mrow = wid * 16 + g;
    uint32_t qf[4][4];
#pragma unroll
    for (int kk = 0; kk < 4; ++kk){
        const __half* p0 = QS + mrow * 72 + kk * 16 + 2 * c;
        qf[kk][0] = ldh2(p0);
        qf[kk][1] = ldh2(p0 + 8 * 72);
        qf[kk][2] = ldh2(p0 + 8);
        qf[kk][3] = ldh2(p0 + 8 * 72 + 8);
    }

    float l_i[2] = {0.f, 0.f};
    float4 o[8];
#pragma unroll
    for (int i = 0; i < 8; ++i) o[i] = make_float4(0.f, 0.f, 0.f, 0.f);

    for (int kb = 0; kb < 18; ++kb){
        if (kb < 16) asm volatile("cp.async.wait_group 1;" ::: "memory");
        else         asm volatile("cp.async.wait_group 0;" ::: "memory");
        __syncthreads();                     // tile kb ready; buf (kb-1)%3 free
        if (kb < 16) load_kv(kb + 2, (kb + 2) % 3);

        const __half* Kb = Kt + (kb % 3) * 32 * KROW;
        const __half* Vb = Vt + (kb % 3) * 64 * 40;

        // S = Q K^T (scale 0.125*log2e already in Q)
        float4 s[4];
#pragma unroll
        for (int i = 0; i < 4; ++i) s[i] = make_float4(0.f, 0.f, 0.f, 0.f);
#pragma unroll
        for (int kk = 0; kk < 4; ++kk){
#pragma unroll
            for (int nf = 0; nf < 4; ++nf){
                const __half* kr = Kb + (nf * 8 + g) * KROW + kk * 16 + 2 * c;
                mmaf16(s[nf], qf[kk][0], qf[kk][1], qf[kk][2], qf[kk][3],
                       ldh2(kr), ldh2(kr + 8));
            }
        }

        // P = 2^s in registers; C-frag -> A-frag identity
        uint32_t pf[4][2];
        float rs0 = 0.f, rs1 = 0.f;
#pragma unroll
        for (int nf = 0; nf < 4; ++nf){
            const float px = ex2f(s[nf].x);
            const float py = ex2f(s[nf].y);
            const float pz = ex2f(s[nf].z);
            const float pw = ex2f(s[nf].w);
            rs0 += px + py; rs1 += pz + pw;
            pf[nf][0] = *(uint32_t*)&(const half2&)__floats2half2_rn(px, py);
            pf[nf][1] = *(uint32_t*)&(const half2&)__floats2half2_rn(pz, pw);
        }
#pragma unroll
        for (int off = 1; off < 4; off <<= 1){
            rs0 += __shfl_xor_sync(0xffffffffu, rs0, off);
            rs1 += __shfl_xor_sync(0xffffffffu, rs1, off);
        }
        l_i[0] += rs0;
        l_i[1] += rs1;

        // O += P V : A = P (regs), B = V^T[d][key] from Vt
#pragma unroll
        for (int kp = 0; kp < 2; ++kp){
            const uint32_t a0 = pf[2 * kp][0];
            const uint32_t a1 = pf[2 * kp][1];
            const uint32_t a2 = pf[2 * kp + 1][0];
            const uint32_t a3 = pf[2 * kp + 1][1];
#pragma unroll
            for (int nf = 0; nf < 8; ++nf){
                const __half* vp = Vb + (nf * 8 + g) * 40 + kp * 16 + 2 * c;
                mmaf16(o[nf], a0, a1, a2, a3, ldh2(vp), ldh2(vp + 8));
            }
        }
    }

    // epilogue: normalize own rows, store token-major directly from C-frags
    const float li0 = 1.f / l_i[0];
    const float li1 = 1.f / l_i[1];
    __half* O0 = g_attn + base + (size_t)(qt * 64 + mrow) * CC + col0;
    __half* O1 = O0 + (size_t)8 * CC;
#pragma unroll
    for (int nf = 0; nf < 8; ++nf){
        *(half2*)(O0 + nf * 8 + 2 * c) = __floats2half2_rn(o[nf].x * li0, o[nf].y * li0);
        *(half2*)(O1 + nf * 8 + 2 * c) = __floats2half2_rn(o[nf].z * li1, o[nf].w * li1);
    }
}

// ---------------------------------------------------------------------------
extern "C" void kernel_launch(void* const* d_in, const int* in_sizes, int n_in,
                              void* d_out, int out_size)
{
    const float* x   = (const float*)d_in[0];
    const float* bq  = (const float*)d_in[2];
    const float* bk  = (const float*)d_in[4];
    const float* bv  = (const float*)d_in[6];
    const float* bo  = (const float*)d_in[8];
    const float* pos = (const float*)d_in[9];
    (void)in_sizes; (void)n_in; (void)out_size;

    cudaFuncSetAttribute(gemm_mma<0>, cudaFuncAttributeMaxDynamicSharedMemorySize, GEMM_SMEM);
    cudaFuncSetAttribute(gemm_mma<1>, cudaFuncAttributeMaxDynamicSharedMemorySize, GEMM_SMEM);
    cudaFuncSetAttribute(attn_mma, cudaFuncAttributeMaxDynamicSharedMemorySize, ATT_SMEM);

    prep_w<<<1024, 256>>>((const float*)d_in[1], (const float*)d_in[3],
                          (const float*)d_in[5], (const float*)d_in[7]);
    transpose_pos<<<dim3(288, 16, 2), 256>>>(x, pos);

    gemm_mma<0><<<dim3(144, 4, 3), 256, GEMM_SMEM>>>(bq, bk, bv, nullptr);

    attn_mma<<<dim3(9, 256), 128, ATT_SMEM>>>();

    gemm_mma<1><<<dim3(144, 4), 256, GEMM_SMEM>>>(bo, nullptr, nullptr, (float*)d_out);
}